// round 2
// baseline (speedup 1.0000x reference)
#include <cuda_runtime.h>
#include <math.h>

#define BB 8
#define TTT 128
#define UU 40
#define WW 1280
#define VOC 32000
#define EMBD 256
#define DECD 512
#define MEMD 512
#define G3 (3*DECD)

#define NEGINF (__int_as_float(0xff800000))

// ---------------- device scratch (no allocation) ----------------
__device__ __align__(16) float g_x[BB*TTT*EMBD];        // 1 MB
__device__ __align__(16) float g_gx[BB*TTT*G3];         // 6.3 MB
__device__ __align__(16) float g_h[2][BB*DECD];         // ping-pong hidden
__device__ __align__(16) float g_rnn[BB*TTT*DECD];      // 2 MB
__device__ __align__(16) float g_uproj[BB*UU*DECD];
__device__ __align__(16) float g_wproj[BB*WW*DECD];     // 20 MB
__device__ __align__(16) float g_pu[BB*TTT*UU];
__device__ __align__(16) float g_sw[BB*TTT*WW];         // 5.2 MB (scores_w -> scores_uw in place)
__device__ __align__(16) float g_X[BB*TTT*(DECD+MEMD)]; // [context | rnn]
__device__ int g_segs[BB*UU];
__device__ int g_sege[BB*UU];
__device__ unsigned g_barc;

// ---------------- helpers ----------------
__device__ __forceinline__ float fast_exp(float x) {
    // FMA-pipe exp via 2^f poly. Valid for x <= 0 (post max-subtraction use).
    x = fmaxf(x, -80.f);
    float t = x * 1.4426950408889634f;
    float n = rintf(t);
    float f = t - n;
    float p = 1.5403530e-4f;
    p = fmaf(p, f, 1.3333558e-3f);
    p = fmaf(p, f, 9.6181291e-3f);
    p = fmaf(p, f, 5.5504109e-2f);
    p = fmaf(p, f, 2.4022651e-1f);
    p = fmaf(p, f, 6.9314718e-1f);
    p = fmaf(p, f, 1.0f);
    int i = (int)n;
    return __int_as_float(__float_as_int(p) + (i << 23));
}

// ---------------- kernels ----------------
__global__ void k_embed(const int* __restrict__ target, const float* __restrict__ emb) {
    int i = blockIdx.x * 256 + threadIdx.x;     // BB*TTT*EMBD
    int row = i >> 8;                           // EMBD == 256
    int col = i & 255;
    g_x[i] = emb[(long)target[row] * EMBD + col];
}

__global__ void k_h0(const float* __restrict__ uo, const int* __restrict__ u_len,
                     const float* __restrict__ W_red, const float* __restrict__ b_red) {
    int b = blockIdx.x;
    __shared__ float enc[DECD];
    int tid = threadIdx.x;                      // 256 threads
    int last = u_len[b] - 1;
    enc[tid]       = uo[((long)b*UU + last)*MEMD + tid];          // fwd_last [0:256)
    enc[256 + tid] = uo[((long)b*UU + 0)*MEMD + 256 + tid];       // bwd_first
    __syncthreads();
    int wrp = tid >> 5, lane = tid & 31;
    for (int d = wrp; d < DECD; d += 8) {
        float s = 0.f;
        const float* wr = &W_red[(long)d*MEMD];
        for (int k = lane; k < MEMD; k += 32) s = fmaf(enc[k], wr[k], s);
        #pragma unroll
        for (int o = 16; o; o >>= 1) s += __shfl_xor_sync(0xffffffffu, s, o);
        if (lane == 0) g_h[0][b*DECD + d] = s + b_red[d];
    }
}

__global__ void k_segbounds(const int* __restrict__ seg_id, const int* __restrict__ w_len) {
    int b = blockIdx.x;
    int tid = threadIdx.x;
    if (tid < UU) g_segs[b*UU + tid] = -1;
    __syncthreads();
    int wl = w_len[b];
    const int* sp = seg_id + (long)b*WW;
    for (int w = tid; w < wl; w += 256) {
        int s = sp[w];
        if (w == 0 || sp[w-1] != s) g_segs[b*UU + s] = w;
        if (w == wl-1 || sp[w+1] != s) g_sege[b*UU + s] = w + 1;
    }
}

__global__ void k_barreset() { if (threadIdx.x == 0) g_barc = 0u; }

// Persistent GRU: 64 blocks x 256 threads. Warp w of block j owns gate-dim d = 8j+w.
// W_hh slice lives in registers (fp32). h broadcast via global ping-pong, read with __ldcg.
__global__ void __launch_bounds__(256) k_gru(const float* __restrict__ W_hh,
                                             const float* __restrict__ b_hh,
                                             const float* __restrict__ gx) {
    __shared__ float s_h[BB][DECD];   // 16 KB
    const int tid  = threadIdx.x;
    const int wrp  = tid >> 5;
    const int lane = tid & 31;
    const int d = blockIdx.x * 8 + wrp;
    float wr[16], wz[16], wn[16];
    #pragma unroll
    for (int i = 0; i < 16; ++i) {
        int k = lane + 32*i;
        wr[i] = W_hh[(long)d*DECD + k];
        wz[i] = W_hh[(long)(DECD + d)*DECD + k];
        wn[i] = W_hh[(long)(2*DECD + d)*DECD + k];
    }
    const float br = b_hh[d], bz = b_hh[DECD + d], bn = b_hh[2*DECD + d];
    const unsigned NB = gridDim.x;

    for (int t = 0; t < TTT; ++t) {
        // prefetch gx for this step (hides L2 latency behind the matvec)
        float pgr = 0.f, pgz = 0.f, pgn = 0.f;
        if (lane < BB) {
            const float* gxp = gx + ((long)(lane*TTT + t)) * G3;
            pgr = gxp[d]; pgz = gxp[DECD + d]; pgn = gxp[2*DECD + d];
        }
        // load h (bypass L1: other SMs wrote it)
        {
            const float4* hsrc = (const float4*)g_h[t & 1];
            float4* dst = (float4*)s_h;
            for (int i = tid; i < (BB*DECD)/4; i += 256) dst[i] = __ldcg(hsrc + i);
        }
        __syncthreads();
        float ar[BB], az[BB], an[BB];
        #pragma unroll
        for (int b = 0; b < BB; ++b) { ar[b] = 0.f; az[b] = 0.f; an[b] = 0.f; }
        #pragma unroll
        for (int i = 0; i < 16; ++i) {
            int k = lane + 32*i;
            #pragma unroll
            for (int b = 0; b < BB; ++b) {
                float hv = s_h[b][k];
                ar[b] = fmaf(wr[i], hv, ar[b]);
                az[b] = fmaf(wz[i], hv, az[b]);
                an[b] = fmaf(wn[i], hv, an[b]);
            }
        }
        #pragma unroll
        for (int b = 0; b < BB; ++b) {
            #pragma unroll
            for (int o = 16; o; o >>= 1) {
                ar[b] += __shfl_xor_sync(0xffffffffu, ar[b], o);
                az[b] += __shfl_xor_sync(0xffffffffu, az[b], o);
                an[b] += __shfl_xor_sync(0xffffffffu, an[b], o);
            }
        }
        if (lane < BB) {
            int b = lane;
            float ghr = ar[b] + br, ghz = az[b] + bz, ghn = an[b] + bn;
            float r = 1.f / (1.f + __expf(-(pgr + ghr)));
            float z = 1.f / (1.f + __expf(-(pgz + ghz)));
            float n = tanhf(pgn + r * ghn);
            float h = s_h[b][d];
            float hn = (1.f - z) * n + z * h;
            g_h[(t+1) & 1][b*DECD + d] = hn;
            long rrow = (long)(b*TTT + t);
            g_rnn[rrow*DECD + d] = hn;
            g_X[rrow*(DECD+MEMD) + MEMD + d] = hn;
        }
        __threadfence();
        __syncthreads();
        if (tid == 0) {
            atomicAdd(&g_barc, 1u);
            unsigned want = (unsigned)(t + 1) * NB;
            while (atomicAdd(&g_barc, 0u) < want) { }
        }
        __syncthreads();
        __threadfence();
    }
}

// Generic SGEMM NT: C[M,N] = A[M,K] * B[N,K]^T + bias[N]. 128x128x8 tiles, 8x8 micro.
__global__ void __launch_bounds__(256, 2) k_gemm_nt(
    const float* __restrict__ A, const float* __restrict__ B,
    const float* __restrict__ bias, float* __restrict__ C,
    int M, int N, int K)
{
    __shared__ float sA[2][8][128];
    __shared__ float sB[2][8][128];
    const int tid = threadIdx.x;
    const int m0 = blockIdx.x * 128;
    const int n0 = blockIdx.y * 128;
    const int lr = tid >> 1;
    const int lc = (tid & 1) << 2;
    const int tx = tid & 15;
    const int ty = tid >> 4;
    const bool aval = (m0 + lr) < M;
    const float* Ap = A + (long)(m0 + lr) * K + lc;
    const float* Bp = B + (long)(n0 + lr) * K + lc;
    float4 av = aval ? *(const float4*)Ap : make_float4(0.f,0.f,0.f,0.f);
    float4 bv = *(const float4*)Bp;
    sA[0][lc+0][lr]=av.x; sA[0][lc+1][lr]=av.y; sA[0][lc+2][lr]=av.z; sA[0][lc+3][lr]=av.w;
    sB[0][lc+0][lr]=bv.x; sB[0][lc+1][lr]=bv.y; sB[0][lc+2][lr]=bv.z; sB[0][lc+3][lr]=bv.w;
    __syncthreads();
    float acc[8][8];
    #pragma unroll
    for (int i = 0; i < 8; ++i)
        #pragma unroll
        for (int j = 0; j < 8; ++j) acc[i][j] = 0.f;
    const int nk = K >> 3;
    for (int kt = 0; kt < nk; ++kt) {
        const int cur = kt & 1;
        if (kt + 1 < nk) {
            av = aval ? *(const float4*)(Ap + (kt+1)*8) : make_float4(0.f,0.f,0.f,0.f);
            bv = *(const float4*)(Bp + (kt+1)*8);
        }
        #pragma unroll
        for (int kk = 0; kk < 8; ++kk) {
            float ra[8], rb[8];
            *(float4*)(ra)   = *(const float4*)&sA[cur][kk][ty*8];
            *(float4*)(ra+4) = *(const float4*)&sA[cur][kk][ty*8+4];
            *(float4*)(rb)   = *(const float4*)&sB[cur][kk][tx*8];
            *(float4*)(rb+4) = *(const float4*)&sB[cur][kk][tx*8+4];
            #pragma unroll
            for (int i = 0; i < 8; ++i)
                #pragma unroll
                for (int j = 0; j < 8; ++j)
                    acc[i][j] = fmaf(ra[i], rb[j], acc[i][j]);
        }
        if (kt + 1 < nk) {
            const int nxt = cur ^ 1;
            sA[nxt][lc+0][lr]=av.x; sA[nxt][lc+1][lr]=av.y; sA[nxt][lc+2][lr]=av.z; sA[nxt][lc+3][lr]=av.w;
            sB[nxt][lc+0][lr]=bv.x; sB[nxt][lc+1][lr]=bv.y; sB[nxt][lc+2][lr]=bv.z; sB[nxt][lc+3][lr]=bv.w;
            __syncthreads();
        }
    }
    const int colb = n0 + tx*8;
    float bb[8];
    #pragma unroll
    for (int j = 0; j < 8; ++j) bb[j] = bias[colb + j];
    #pragma unroll
    for (int i = 0; i < 8; ++i) {
        int row = m0 + ty*8 + i;
        if (row < M) {
            float* Cp = C + (long)row * N + colb;
            float4 o1, o2;
            o1.x = acc[i][0]+bb[0]; o1.y = acc[i][1]+bb[1]; o1.z = acc[i][2]+bb[2]; o1.w = acc[i][3]+bb[3];
            o2.x = acc[i][4]+bb[4]; o2.y = acc[i][5]+bb[5]; o2.z = acc[i][6]+bb[6]; o2.w = acc[i][7]+bb[7];
            *(float4*)Cp = o1; *(float4*)(Cp+4) = o2;
        }
    }
}

// Batched NT: scores_w[b] = rnn[b](128x512) * wproj[b]^T(1280x512), mask -> g_sw.
__global__ void __launch_bounds__(256) k_scores_w(const int* __restrict__ w_len) {
    __shared__ float sA[16][64];
    __shared__ float sB[16][64];
    const int b = blockIdx.z;
    const int t0 = blockIdx.y * 64;
    const int w0 = blockIdx.x * 64;
    const float* A  = g_rnn   + (long)b*TTT*DECD;
    const float* Bm = g_wproj + (long)b*WW*DECD;
    const int tid = threadIdx.x;
    const int lr = tid >> 2;
    const int lc = (tid & 3) << 2;
    const int tx = tid & 15;
    const int ty = tid >> 4;
    float acc[4][4];
    #pragma unroll
    for (int i = 0; i < 4; ++i)
        #pragma unroll
        for (int j = 0; j < 4; ++j) acc[i][j] = 0.f;
    for (int k0 = 0; k0 < DECD; k0 += 16) {
        float4 av = *(const float4*)(A  + (long)(t0+lr)*DECD + k0 + lc);
        float4 bv = *(const float4*)(Bm + (long)(w0+lr)*DECD + k0 + lc);
        __syncthreads();
        sA[lc+0][lr]=av.x; sA[lc+1][lr]=av.y; sA[lc+2][lr]=av.z; sA[lc+3][lr]=av.w;
        sB[lc+0][lr]=bv.x; sB[lc+1][lr]=bv.y; sB[lc+2][lr]=bv.z; sB[lc+3][lr]=bv.w;
        __syncthreads();
        #pragma unroll
        for (int kk = 0; kk < 16; ++kk) {
            float4 ra = *(const float4*)&sA[kk][ty*4];
            float4 rb = *(const float4*)&sB[kk][tx*4];
            float pa[4] = {ra.x, ra.y, ra.z, ra.w};
            float pb[4] = {rb.x, rb.y, rb.z, rb.w};
            #pragma unroll
            for (int i = 0; i < 4; ++i)
                #pragma unroll
                for (int j = 0; j < 4; ++j)
                    acc[i][j] = fmaf(pa[i], pb[j], acc[i][j]);
        }
    }
    const int wl = w_len[b];
    #pragma unroll
    for (int i = 0; i < 4; ++i) {
        int t = t0 + ty*4 + i;
        #pragma unroll
        for (int j = 0; j < 4; ++j) {
            int w = w0 + tx*4 + j;
            g_sw[((long)(b*TTT + t))*WW + w] = (w < wl) ? acc[i][j] : NEGINF;
        }
    }
}

// scores_u + masked softmax over U -> pu (probabilities).
__global__ void __launch_bounds__(256) k_pu(const int* __restrict__ u_len) {
    const int bt = blockIdx.x;
    const int b = bt >> 7;
    __shared__ float s_r[DECD];
    __shared__ float s_sc[UU];
    __shared__ float s_e[UU];
    const int tid = threadIdx.x, lane = tid & 31, wrp = tid >> 5;
    const float* rrow = g_rnn + (long)bt * DECD;
    s_r[tid] = rrow[tid]; s_r[tid+256] = rrow[tid+256];
    __syncthreads();
    const int ul = u_len[b];
    for (int u = wrp; u < UU; u += 8) {
        const float* up = g_uproj + (long)(b*UU + u) * DECD;
        float s = 0.f;
        for (int k = lane; k < DECD; k += 32) s = fmaf(s_r[k], up[k], s);
        #pragma unroll
        for (int o = 16; o; o >>= 1) s += __shfl_xor_sync(0xffffffffu, s, o);
        if (lane == 0) s_sc[u] = (u < ul) ? s : NEGINF;
    }
    __syncthreads();
    if (tid == 0) {
        float m = NEGINF;
        for (int u = 0; u < UU; ++u) m = fmaxf(m, s_sc[u]);
        float sum = 0.f;
        for (int u = 0; u < UU; ++u) { float e = fast_exp(s_sc[u] - m); s_e[u] = e; sum += e; }
        float inv = 1.f / sum;
        for (int u = 0; u < UU; ++u) g_pu[(long)bt*UU + u] = s_e[u] * inv;
    }
}

// Segment softmax over w (within seg_id groups), times pu  -> scores_uw in place.
__global__ void __launch_bounds__(256) k_segsoft(const int* __restrict__ w_len) {
    const int bt = blockIdx.x;
    const int b = bt >> 7;
    float* row = g_sw + (long)bt * WW;
    const int tid = threadIdx.x, lane = tid & 31, wrp = tid >> 5;
    for (int u = wrp; u < UU; u += 8) {
        int s = g_segs[b*UU + u];
        if (s < 0) continue;
        int e = g_sege[b*UU + u];
        float m = -1e30f;
        for (int w = s + lane; w < e; w += 32) m = fmaxf(m, row[w]);
        #pragma unroll
        for (int o = 16; o; o >>= 1) m = fmaxf(m, __shfl_xor_sync(0xffffffffu, m, o));
        float sum = 0.f;
        for (int w = s + lane; w < e; w += 32) sum += fast_exp(row[w] - m);
        #pragma unroll
        for (int o = 16; o; o >>= 1) sum += __shfl_xor_sync(0xffffffffu, sum, o);
        float pu = g_pu[(long)bt*UU + u];
        float inv = pu / fmaxf(sum, 1e-30f);
        for (int w = s + lane; w < e; w += 32) row[w] = fast_exp(row[w] - m) * inv;
    }
    const int wl = w_len[b];
    for (int w = wl + tid; w < WW; w += 256) row[w] = 0.f;
}

// Batched NN: context[b] = scores_uw[b](128x1280) * w_output[b](1280x512) -> g_X[:, :512].
__global__ void __launch_bounds__(256) k_context(const float* __restrict__ w_output) {
    __shared__ float sA[16][64];
    __shared__ float sB[16][64];
    const int b = blockIdx.z;
    const int t0 = blockIdx.y * 64;
    const int n0 = blockIdx.x * 64;
    const float* A  = g_sw + (long)b*TTT*WW;
    const float* Bm = w_output + (long)b*WW*MEMD;
    const int tid = threadIdx.x;
    const int lr = tid >> 2;
    const int lc = (tid & 3) << 2;
    const int kr = tid >> 4;
    const int kc = (tid & 15) << 2;
    const int tx = tid & 15;
    const int ty = tid >> 4;
    float acc[4][4];
    #pragma unroll
    for (int i = 0; i < 4; ++i)
        #pragma unroll
        for (int j = 0; j < 4; ++j) acc[i][j] = 0.f;
    for (int k0 = 0; k0 < WW; k0 += 16) {
        float4 av = *(const float4*)(A  + (long)(t0+lr)*WW + k0 + lc);
        float4 bv = *(const float4*)(Bm + (long)(k0+kr)*MEMD + n0 + kc);
        __syncthreads();
        sA[lc+0][lr]=av.x; sA[lc+1][lr]=av.y; sA[lc+2][lr]=av.z; sA[lc+3][lr]=av.w;
        *(float4*)&sB[kr][kc] = bv;
        __syncthreads();
        #pragma unroll
        for (int kk = 0; kk < 16; ++kk) {
            float4 ra = *(const float4*)&sA[kk][ty*4];
            float4 rb = *(const float4*)&sB[kk][tx*4];
            float pa[4] = {ra.x, ra.y, ra.z, ra.w};
            float pb[4] = {rb.x, rb.y, rb.z, rb.w};
            #pragma unroll
            for (int i = 0; i < 4; ++i)
                #pragma unroll
                for (int j = 0; j < 4; ++j)
                    acc[i][j] = fmaf(pa[i], pb[j], acc[i][j]);
        }
    }
    #pragma unroll
    for (int i = 0; i < 4; ++i) {
        int t = t0 + ty*4 + i;
        #pragma unroll
        for (int j = 0; j < 4; ++j) {
            int n = n0 + tx*4 + j;
            g_X[((long)(b*TTT + t))*(DECD+MEMD) + n] = acc[i][j];
        }
    }
}

// In-place row log_softmax over VOC.
__global__ void __launch_bounds__(256) k_logsoftmax(float* __restrict__ out) {
    float4* p = (float4*)(out + (long)blockIdx.x * VOC);
    const int n4 = VOC / 4;
    const int tid = threadIdx.x, lane = tid & 31, wrp = tid >> 5;
    __shared__ float sred[8];
    float m = -1e30f;
    for (int v = tid; v < n4; v += 256) {
        float4 x = p[v];
        m = fmaxf(m, fmaxf(fmaxf(x.x, x.y), fmaxf(x.z, x.w)));
    }
    #pragma unroll
    for (int o = 16; o; o >>= 1) m = fmaxf(m, __shfl_xor_sync(0xffffffffu, m, o));
    if (lane == 0) sred[wrp] = m;
    __syncthreads();
    float bm = sred[0];
    #pragma unroll
    for (int i = 1; i < 8; ++i) bm = fmaxf(bm, sred[i]);
    __syncthreads();
    float s = 0.f;
    for (int v = tid; v < n4; v += 256) {
        float4 x = p[v];
        s += fast_exp(x.x-bm) + fast_exp(x.y-bm) + fast_exp(x.z-bm) + fast_exp(x.w-bm);
    }
    #pragma unroll
    for (int o = 16; o; o >>= 1) s += __shfl_xor_sync(0xffffffffu, s, o);
    if (lane == 0) sred[wrp] = s;
    __syncthreads();
    float bs = 0.f;
    #pragma unroll
    for (int i = 0; i < 8; ++i) bs += sred[i];
    const float lz = bm + logf(bs);
    for (int v = tid; v < n4; v += 256) {
        float4 x = p[v];
        x.x -= lz; x.y -= lz; x.z -= lz; x.w -= lz;
        p[v] = x;
    }
}

// ---------------- host ----------------
extern "C" void kernel_launch(void* const* d_in, const int* in_sizes, int n_in,
                              void* d_out, int out_size) {
    const int*   target = (const int*)  d_in[0];
    const int*   seg_id = (const int*)  d_in[1];
    const int*   u_len  = (const int*)  d_in[2];
    const int*   w_len  = (const int*)  d_in[3];
    const float* u_out  = (const float*)d_in[4];
    const float* w_out  = (const float*)d_in[5];
    const float* emb    = (const float*)d_in[6];
    const float* W_red  = (const float*)d_in[7];
    const float* b_red  = (const float*)d_in[8];
    const float* W_ih   = (const float*)d_in[9];
    const float* W_hh   = (const float*)d_in[10];
    const float* b_ih   = (const float*)d_in[11];
    const float* b_hh   = (const float*)d_in[12];
    const float* W_au   = (const float*)d_in[13];
    const float* b_au   = (const float*)d_in[14];
    const float* W_aw   = (const float*)d_in[15];
    const float* b_aw   = (const float*)d_in[16];
    const float* W_outp = (const float*)d_in[17];
    const float* b_outp = (const float*)d_in[18];
    float* out = (float*)d_out;

    float *p_x, *p_gx, *p_up, *p_wp, *p_X;
    cudaGetSymbolAddress((void**)&p_x,  g_x);
    cudaGetSymbolAddress((void**)&p_gx, g_gx);
    cudaGetSymbolAddress((void**)&p_up, g_uproj);
    cudaGetSymbolAddress((void**)&p_wp, g_wproj);
    cudaGetSymbolAddress((void**)&p_X,  g_X);

    k_embed<<<(BB*TTT*EMBD)/256, 256>>>(target, emb);
    k_h0<<<BB, 256>>>(u_out, u_len, W_red, b_red);
    k_segbounds<<<BB, 256>>>(seg_id, w_len);
    // gx = x @ W_ih^T + b_ih   (1024 x 1536 x 256)
    k_gemm_nt<<<dim3(8, 12), 256>>>(p_x, W_ih, b_ih, p_gx, BB*TTT, G3, EMBD);
    // u_proj / w_proj
    k_gemm_nt<<<dim3(3, 4), 256>>>(u_out, W_au, b_au, p_up, BB*UU, DECD, MEMD);
    k_gemm_nt<<<dim3(80, 4), 256>>>(w_out, W_aw, b_aw, p_wp, BB*WW, DECD, MEMD);
    // GRU (persistent; grid barrier)
    k_barreset<<<1, 32>>>();
    k_gru<<<64, 256>>>(W_hh, b_hh, p_gx);
    // attention over U and W
    k_pu<<<BB*TTT, 256>>>(u_len);
    k_scores_w<<<dim3(WW/64, TTT/64, BB), 256>>>(w_len);
    k_segsoft<<<BB*TTT, 256>>>(w_len);
    k_context<<<dim3(MEMD/64, TTT/64, BB), 256>>>(w_out);
    // final logits + log_softmax
    k_gemm_nt<<<dim3(8, 250), 256>>>(p_X, W_outp, b_outp, out, BB*TTT, VOC, DECD+MEMD);
    k_logsoftmax<<<BB*TTT, 256>>>(out);
    (void)in_sizes; (void)n_in; (void)out_size;
}